// round 6
// baseline (speedup 1.0000x reference)
#include <cuda_runtime.h>

// FastECT: per-(batch,bin,theta) histogram + cumsum over bins.
// N=200000 pts (D=3), T=128 thetas, R=128 bins, B=64 batches, batch sorted.
//
// k_zero: zero d_out (poisoned 0xAA).
// k_hist: 1776 blocks (=148 SMs x 12 resident) x 128 threads over flat equal
//   point ranges. Histogram: u8 counts, 4 bins packed per 32-bit word per
//   thread: byte addr = (bin>>2)*512 + t*4 + (bin&3). Word index =
//   (bin>>2)*128 + t -> bank = t%32 for ANY bin => every RMW / flush / zero
//   is exactly conflict-free. Thread t owns theta t => race-free, no atomics
//   in the hot loop. u8 exact: per-segment counts <= points/block = 113 < 256.
//   cumsum is linear => each block flushes cumsum(partial) into d_out with
//   f32 atomicAdd (exact integer adds, deterministic).

#define TT 128
#define RR 128
#define NBLK 1776    // 148 SMs * 12 resident blocks, single balanced wave
#define TILE 128     // points staged per tile (float4 each) -> 2KB stage

typedef unsigned int  u32;
typedef unsigned char u8;

__device__ __forceinline__ int lower_bound_i32(const int* __restrict__ a, int n, int key) {
    int lo = 0, hi = n;
    while (lo < hi) {
        int mid = (lo + hi) >> 1;
        if (a[mid] < key) lo = mid + 1; else hi = mid;
    }
    return lo;
}

// bin = clip(floor((x.v + 1) * 64), 0, 127); float-clamp is exactly equivalent
// (f<0 -> 0, f in [0,128) -> floor, f>=128 -> 127) and runs on the fma pipe.
__device__ __forceinline__ int bin_of(float x0, float x1, float x2,
                                      float v0, float v1, float v2) {
    float nh = fmaf(x2, v2, fmaf(x1, v1, __fmul_rn(x0, v0)));
    float f  = __fmul_rn(__fadd_rn(nh, 1.0f), 64.0f);
    f = fminf(fmaxf(f, 0.0f), 127.0f);
    return __float2int_rd(f);
}

extern __shared__ u8 smem_dyn[];

__global__ void __launch_bounds__(256)
k_zero(float* __restrict__ out, int n4) {
    int i = blockIdx.x * blockDim.x + threadIdx.x;
    if (i < n4) ((float4*)out)[i] = make_float4(0.f, 0.f, 0.f, 0.f);
}

__global__ void __launch_bounds__(128, 12)
k_hist(const float* __restrict__ x, const float* __restrict__ v,
       const int* __restrict__ batch, int n, float* __restrict__ out) {
    u8* h = smem_dyn;                                // [RR*TT] u8, packed
    float4* xs4 = (float4*)(smem_dyn + RR * TT);     // [TILE] staged points
    __shared__ int seg_end_sh;

    const int t = threadIdx.x;
    const int g = blockIdx.x;
    u8* hbase = h + (t << 2);                        // per-thread word base

    const int lo = (int)(((long long)g)     * n / NBLK);
    const int hi = (int)(((long long)g + 1) * n / NBLK);

    const float v0 = v[t];
    const float v1 = v[TT + t];
    const float v2 = v[2 * TT + t];

    // zero 16KB histogram as uint4 (conflict-free)
    {
        uint4* hz = (uint4*)h;
        for (int i = t; i < (RR * TT) / 16; i += 128)
            hz[i] = make_uint4(0u, 0u, 0u, 0u);
    }

    int pos = lo;
    while (pos < hi) {
        if (t == 0) {
            int b = batch[pos];
            seg_end_sh = min(hi, lower_bound_i32(batch, n, b + 1));
        }
        __syncthreads();
        const int seg_end = seg_end_sh;
        const int b = batch[pos];                    // uniform broadcast

        for (int base = pos; base < seg_end; base += TILE) {
            const int m = min(TILE, seg_end - base);
            if (t < m) {
                const float* src = x + (size_t)(base + t) * 3;
                xs4[t] = make_float4(src[0], src[1], src[2], 0.0f);
            }
            __syncthreads();

            int k = 0;
            for (; k + 8 <= m; k += 8) {
                int bn[8];
#pragma unroll
                for (int j = 0; j < 8; ++j) {
                    float4 p = xs4[k + j];
                    bn[j] = bin_of(p.x, p.y, p.z, v0, v1, v2);
                }
#pragma unroll
                for (int j = 0; j < 8; ++j) {
                    u8* a = hbase + (bn[j] >> 2) * 512 + (bn[j] & 3);
                    *a = (u8)(*a + 1);               // exclusive slot
                }
            }
            for (; k < m; ++k) {
                float4 p = xs4[k];
                int bn = bin_of(p.x, p.y, p.z, v0, v1, v2);
                u8* a = hbase + (bn >> 2) * 512 + (bn & 3);
                *a = (u8)(*a + 1);
            }
            __syncthreads();
        }

        // flush: cumsum(own partial) += into out[b][bin][t].
        // One LDS.32 per 4 bins (word (bin>>2)*128 + t, bank t%32), REDG coalesced.
        {
            int acc = 0;
            u32* hw = (u32*)h;
            float* dst = out + ((size_t)b * RR) * TT + t;
#pragma unroll 4
            for (int bin4 = 0; bin4 < RR / 4; ++bin4) {
                u32 w = hw[bin4 * 128 + t];
                hw[bin4 * 128 + t] = 0u;             // rezero for next segment
                acc += (int)(w & 255u);
                atomicAdd(dst + (size_t)(bin4 * 4 + 0) * TT, (float)acc);
                acc += (int)((w >> 8) & 255u);
                atomicAdd(dst + (size_t)(bin4 * 4 + 1) * TT, (float)acc);
                acc += (int)((w >> 16) & 255u);
                atomicAdd(dst + (size_t)(bin4 * 4 + 2) * TT, (float)acc);
                acc += (int)(w >> 24);
                atomicAdd(dst + (size_t)(bin4 * 4 + 3) * TT, (float)acc);
            }
        }
        pos = seg_end;
        __syncthreads();                             // protect xs4 / h reuse
    }
}

extern "C" void kernel_launch(void* const* d_in, const int* in_sizes, int n_in,
                              void* d_out, int out_size) {
    const float* x     = (const float*)d_in[0];   // [200000, 3]
    const float* v     = (const float*)d_in[1];   // [3, 128]
    const int*   batch = (const int*)d_in[2];     // [200000], sorted
    const int n = in_sizes[2];

    float* out = (float*)d_out;                   // [64, 128, 128]
    const int n4 = out_size / 4;

    const int smem_bytes = RR * TT + TILE * 16;   // 16384 + 2048 = 18432
    cudaFuncSetAttribute(k_hist, cudaFuncAttributeMaxDynamicSharedMemorySize, smem_bytes);

    k_zero<<<(n4 + 255) / 256, 256>>>(out, n4);
    k_hist<<<NBLK, 128, smem_bytes>>>(x, v, batch, n, out);
}

// round 7
// speedup vs baseline: 1.2538x; 1.2538x over previous
#include <cuda_runtime.h>

// FastECT: per-(batch,bin,theta) histogram + cumsum over bins.
// N=200000 pts (D=3), T=128 thetas, R=128 bins, B=64 batches, batch sorted.
//
// k_hist: 592 blocks (=148 SMs x 4) x 128 threads over flat equal point
//   ranges (fatter blocks amortize the per-block zero+flush overhead, which
//   R5->R6 showed costs ~5us per +592 blocks). Histogram: u8 counts, 4 bins
//   per 32-bit word per thread (word = (bin>>2)*128 + t -> bank t%32 for any
//   bin: every RMW/flush/zero conflict-free). Thread t owns theta t =>
//   race-free, no atomics in the hot loop.
//   Points staged SoA (sx/sy/sz) so one LDS.128 gives two packed (p0,p1)
//   component pairs -> bin math in f32x2 (FFMA2) at half the fma-pipe ops,
//   bit-identical per-lane rounding. cumsum is linear => each block flushes
//   cumsum(partial) into d_out via f32 atomicAdd (exact integer adds).

#define TT 128
#define RR 128
#define NBLK 592     // 148 SMs * 4 resident blocks, single balanced wave
#define TILE 512     // points staged per tile (SoA, 3*2KB)

typedef unsigned int       u32;
typedef unsigned char      u8;
typedef unsigned long long u64;

__device__ __forceinline__ int lower_bound_i32(const int* __restrict__ a, int n, int key) {
    int lo = 0, hi = n;
    while (lo < hi) {
        int mid = (lo + hi) >> 1;
        if (a[mid] < key) lo = mid + 1; else hi = mid;
    }
    return lo;
}

// packed f32x2 helpers (sm_103a): same per-lane rounding as scalar chain
__device__ __forceinline__ u64 pack2(float lo, float hi) {
    u64 r;
    asm("mov.b64 %0, {%1, %2};" : "=l"(r) : "f"(lo), "f"(hi));
    return r;
}
__device__ __forceinline__ void unpack2(u64 v, float& lo, float& hi) {
    asm("mov.b64 {%0, %1}, %2;" : "=f"(lo), "=f"(hi) : "l"(v));
}
__device__ __forceinline__ u64 mul2(u64 a, u64 b) {
    u64 r; asm("mul.rn.f32x2 %0, %1, %2;" : "=l"(r) : "l"(a), "l"(b)); return r;
}
__device__ __forceinline__ u64 add2(u64 a, u64 b) {
    u64 r; asm("add.rn.f32x2 %0, %1, %2;" : "=l"(r) : "l"(a), "l"(b)); return r;
}
__device__ __forceinline__ u64 fma2(u64 a, u64 b, u64 c) {
    u64 r; asm("fma.rn.f32x2 %0, %1, %2, %3;" : "=l"(r) : "l"(a), "l"(b), "l"(c)); return r;
}

// scalar bin (tail path): clip(floor((x.v + 1)*64), 0, 127)
__device__ __forceinline__ int bin_of(float x0, float x1, float x2,
                                      float v0, float v1, float v2) {
    float nh = fmaf(x2, v2, fmaf(x1, v1, __fmul_rn(x0, v0)));
    float f  = __fmul_rn(__fadd_rn(nh, 1.0f), 64.0f);
    f = fminf(fmaxf(f, 0.0f), 127.0f);
    return __float2int_rd(f);
}
__device__ __forceinline__ int clampf2i(float f) {
    return __float2int_rd(fminf(fmaxf(f, 0.0f), 127.0f));
}

extern __shared__ u8 smem_dyn[];

__global__ void __launch_bounds__(256)
k_zero(float* __restrict__ out, int n4) {
    int i = blockIdx.x * blockDim.x + threadIdx.x;
    if (i < n4) ((float4*)out)[i] = make_float4(0.f, 0.f, 0.f, 0.f);
}

__global__ void __launch_bounds__(128, 4)
k_hist(const float* __restrict__ x, const float* __restrict__ v,
       const int* __restrict__ batch, int n, float* __restrict__ out) {
    u8*    h  = smem_dyn;                        // [RR*TT] u8 packed hist
    float* sx = (float*)(smem_dyn + RR * TT);    // [TILE] SoA stage
    float* sy = sx + TILE;
    float* sz = sy + TILE;
    __shared__ int seg_end_sh;

    const int t = threadIdx.x;
    const int g = blockIdx.x;
    u8* hbase = h + (t << 2);                    // per-thread word base

    const int lo = (int)(((long long)g)     * n / NBLK);
    const int hi = (int)(((long long)g + 1) * n / NBLK);

    const float v0 = v[t];
    const float v1 = v[TT + t];
    const float v2 = v[2 * TT + t];
    const u64 v0p = pack2(v0, v0), v1p = pack2(v1, v1), v2p = pack2(v2, v2);
    const u64 onep = pack2(1.0f, 1.0f), c64p = pack2(64.0f, 64.0f);

    // zero 16KB histogram as uint4 (conflict-free)
    {
        uint4* hz = (uint4*)h;
        for (int i = t; i < (RR * TT) / 16; i += 128)
            hz[i] = make_uint4(0u, 0u, 0u, 0u);
    }

    int pos = lo;
    while (pos < hi) {
        if (t == 0) {
            int b = batch[pos];
            seg_end_sh = min(hi, lower_bound_i32(batch, n, b + 1));
        }
        __syncthreads();
        const int seg_end = seg_end_sh;
        const int b = batch[pos];                // uniform broadcast

        for (int base = pos; base < seg_end; base += TILE) {
            const int m = min(TILE, seg_end - base);
            for (int p = t; p < m; p += 128) {   // SoA stage, amortized /128
                const float* src = x + (size_t)(base + p) * 3;
                sx[p] = src[0]; sy[p] = src[1]; sz[p] = src[2];
            }
            __syncthreads();

            int k = 0;
            for (; k + 4 <= m; k += 4) {
                // LDS.128 -> two naturally packed f32x2 pairs per component
                ulonglong2 X = *(const ulonglong2*)(sx + k);
                ulonglong2 Y = *(const ulonglong2*)(sy + k);
                ulonglong2 Z = *(const ulonglong2*)(sz + k);
                u64 nhA = fma2(Z.x, v2p, fma2(Y.x, v1p, mul2(X.x, v0p)));
                u64 nhB = fma2(Z.y, v2p, fma2(Y.y, v1p, mul2(X.y, v0p)));
                u64 fA  = mul2(add2(nhA, onep), c64p);
                u64 fB  = mul2(add2(nhB, onep), c64p);
                float f0, f1, f2, f3;
                unpack2(fA, f0, f1);
                unpack2(fB, f2, f3);
                int b0 = clampf2i(f0), b1 = clampf2i(f1);
                int b2 = clampf2i(f2), b3 = clampf2i(f3);
                u8* a0 = hbase + (b0 >> 2) * 512 + (b0 & 3);
                u8* a1 = hbase + (b1 >> 2) * 512 + (b1 & 3);
                u8* a2 = hbase + (b2 >> 2) * 512 + (b2 & 3);
                u8* a3 = hbase + (b3 >> 2) * 512 + (b3 & 3);
                *a0 = (u8)(*a0 + 1);             // exclusive slots, race-free
                *a1 = (u8)(*a1 + 1);
                *a2 = (u8)(*a2 + 1);
                *a3 = (u8)(*a3 + 1);
            }
            for (; k < m; ++k) {
                int bn = bin_of(sx[k], sy[k], sz[k], v0, v1, v2);
                u8* a = hbase + (bn >> 2) * 512 + (bn & 3);
                *a = (u8)(*a + 1);
            }
            __syncthreads();
        }

        // flush: cumsum(own partial) += out[b][bin][t]; fully unrolled so
        // REDG offsets become immediates. LDS word (bin>>2)*128+t, bank t%32.
        {
            int acc = 0;
            u32* hw = (u32*)h;
            float* dst = out + ((size_t)b * RR) * TT + t;
#pragma unroll
            for (int bin4 = 0; bin4 < RR / 4; ++bin4) {
                u32 w = hw[bin4 * 128 + t];
                hw[bin4 * 128 + t] = 0u;         // rezero for next segment
                acc += (int)(w & 255u);
                atomicAdd(dst + (bin4 * 4 + 0) * TT, (float)acc);
                acc += (int)((w >> 8) & 255u);
                atomicAdd(dst + (bin4 * 4 + 1) * TT, (float)acc);
                acc += (int)((w >> 16) & 255u);
                atomicAdd(dst + (bin4 * 4 + 2) * TT, (float)acc);
                acc += (int)(w >> 24);
                atomicAdd(dst + (bin4 * 4 + 3) * TT, (float)acc);
            }
        }
        pos = seg_end;
        __syncthreads();                         // protect stage/hist reuse
    }
}

extern "C" void kernel_launch(void* const* d_in, const int* in_sizes, int n_in,
                              void* d_out, int out_size) {
    const float* x     = (const float*)d_in[0];   // [200000, 3]
    const float* v     = (const float*)d_in[1];   // [3, 128]
    const int*   batch = (const int*)d_in[2];     // [200000], sorted
    const int n = in_sizes[2];

    float* out = (float*)d_out;                   // [64, 128, 128]
    const int n4 = out_size / 4;

    const int smem_bytes = RR * TT + 3 * TILE * 4;   // 16384 + 6144 = 22528
    cudaFuncSetAttribute(k_hist, cudaFuncAttributeMaxDynamicSharedMemorySize, smem_bytes);

    k_zero<<<(n4 + 255) / 256, 256>>>(out, n4);
    k_hist<<<NBLK, 128, smem_bytes>>>(x, v, batch, n, out);
}